// round 9
// baseline (speedup 1.0000x reference)
#include <cuda_runtime.h>
#include <cstdint>
#include <math.h>

#define BB 64
#define MM 8192
#define VV 128
#define FEPS 1e-8f
#define SEL_CAP 1024
#define BLOCKS_PER_B (MM / 64)   // 128 blocks per batch

// Scratch (device globals: no allocation allowed in kernel_launch)
__device__ unsigned g_keys[BB * MM];   // 2 MB order-preserving keys
__device__ int      g_counter[BB];     // zero-init; reset by selecting block

// ---- order-preserving float<->uint key mapping (larger float => larger key) ----
__device__ __forceinline__ unsigned f2k(float f) {
    unsigned b = __float_as_uint(f);
    return (b & 0x80000000u) ? ~b : (b | 0x80000000u);
}
__device__ __forceinline__ float k2f(unsigned u) {
    unsigned b = (u & 0x80000000u) ? (u ^ 0x80000000u) : ~u;
    return __uint_as_float(b);
}

// ============================================================================
// FUSED kernel. Phase A (all blocks): sim for 64 rows (R6-proven layout:
// 8 lanes/row, 4 rows/warp, 8 independent streaming LDG.128 per thread),
// stored as order-preserving uint keys. Phase B (last-arriving block per
// batch): 4-round radix select + compaction + weighted read, with the batch's
// keys re-read from L2. Only the final batch's select is exposed as tail.
// Grid: (MM/64, BB), 256 threads.
// ============================================================================
__global__ void __launch_bounds__(256) fused_kernel(
        const float* __restrict__ mem,
        const float* __restrict__ vin,
        const int*   __restrict__ topk_ptr,
        float*       __restrict__ out) {
    __shared__ __align__(16) float sv[VV];
    __shared__ float    s_nb;
    __shared__ int      s_last;
    // select/read state (used only by the last block per batch)
    __shared__ int      hist[256];
    __shared__ int      wsum[8];
    __shared__ unsigned s_prefix;
    __shared__ int      s_k, s_cnt;
    __shared__ int      s_idx[SEL_CAP];
    __shared__ float    s_w[SEL_CAP];
    __shared__ float    s_part[2][VV];
    __shared__ float    s_sw2;

    const int b   = blockIdx.y;
    const int tid = threadIdx.x;

    // ---------------- Phase A: similarity for this block's 64 rows ----------
    if (tid < VV) sv[tid] = vin[b * VV + tid] + FEPS;
    __syncthreads();
    if (tid < 32) {
        float s = 0.f;
        #pragma unroll
        for (int i = tid; i < VV; i += 32) { float x = sv[i]; s += x * x; }
        #pragma unroll
        for (int o = 16; o; o >>= 1) s += __shfl_xor_sync(0xffffffffu, s, o);
        if (tid == 0) s_nb = sqrtf(s);
    }
    __syncthreads();

    {
        const float nb   = s_nb;
        const int   warp = tid >> 5;
        const int   lane = tid & 31;
        const int   rw   = lane >> 3;   // row within warp's 4-row group
        const int   s    = lane & 7;    // float4 segment within row (0..7)

        const float4* svq = reinterpret_cast<const float4*>(sv);
        const float4 q0 = svq[s], q1 = svq[s + 8], q2 = svq[s + 16], q3 = svq[s + 24];

        const int m0 = blockIdx.x * 64 + warp * 4 + rw;
        const int m1 = m0 + 32;
        const float4* rowA = reinterpret_cast<const float4*>(mem + ((size_t)b * MM + m0) * VV);
        const float4* rowB = reinterpret_cast<const float4*>(mem + ((size_t)b * MM + m1) * VV);

        float4 a0 = __ldcs(rowA + s);      float4 a1 = __ldcs(rowA + s + 8);
        float4 a2 = __ldcs(rowA + s + 16); float4 a3 = __ldcs(rowA + s + 24);
        float4 b0 = __ldcs(rowB + s);      float4 b1 = __ldcs(rowB + s + 8);
        float4 b2 = __ldcs(rowB + s + 16); float4 b3 = __ldcs(rowB + s + 24);

        float numA = 0.f, ssA = 0.f, numB = 0.f, ssB = 0.f;
        #define ACC(X, Q, NUM, SS)                                        \
            { float e0 = X.x + FEPS, e1 = X.y + FEPS,                     \
                    e2 = X.z + FEPS, e3 = X.w + FEPS;                     \
              NUM += e0 * Q.x + e1 * Q.y + e2 * Q.z + e3 * Q.w;           \
              SS  += e0 * e0 + e1 * e1 + e2 * e2 + e3 * e3; }
        ACC(a0, q0, numA, ssA) ACC(a1, q1, numA, ssA)
        ACC(a2, q2, numA, ssA) ACC(a3, q3, numA, ssA)
        ACC(b0, q0, numB, ssB) ACC(b1, q1, numB, ssB)
        ACC(b2, q2, numB, ssB) ACC(b3, q3, numB, ssB)
        #undef ACC

        #pragma unroll
        for (int o = 4; o; o >>= 1) {
            numA += __shfl_xor_sync(0xffffffffu, numA, o);
            ssA  += __shfl_xor_sync(0xffffffffu, ssA,  o);
            numB += __shfl_xor_sync(0xffffffffu, numB, o);
            ssB  += __shfl_xor_sync(0xffffffffu, ssB,  o);
        }
        if (s == 0) {
            g_keys[b * MM + m0] = f2k(numA / fmaxf(sqrtf(ssA) * nb, FEPS));
            g_keys[b * MM + m1] = f2k(numB / fmaxf(sqrtf(ssB) * nb, FEPS));
        }
    }

    // ---------------- arrival: last block per batch proceeds ----------------
    __syncthreads();
    if (tid == 0) {
        __threadfence();                              // publish this block's keys
        int done = atomicAdd(&g_counter[b], 1);
        s_last = (done == BLOCKS_PER_B - 1);
    }
    __syncthreads();
    if (!s_last) return;
    if (tid == 0) __threadfence();                    // acquire others' keys
    __syncthreads();

    // ---------------- Phase B: select + read for batch b --------------------
    const unsigned* keys = &g_keys[b * MM];
    const int lane = tid & 31;

    if (tid == 0) { s_prefix = 0u; s_k = *topk_ptr; s_cnt = 0; }
    __syncthreads();

    #pragma unroll
    for (int round = 0; round < 4; round++) {
        const int shift = 24 - 8 * round;
        hist[tid & 255] = 0;          // 256 threads cover 256 bins exactly
        __syncthreads();
        const unsigned pmask  = (round == 0) ? 0u : (0xFFFFFFFFu << (shift + 8));
        const unsigned prefix = s_prefix;
        for (int i = tid; i < MM; i += 256) {
            unsigned u = __ldg(&keys[i]);
            if ((u & pmask) == prefix)
                atomicAdd(&hist[(u >> shift) & 255], 1);
        }
        __syncthreads();
        // parallel suffix pick: thread t handles bin r = 255 - t
        {
            const int r = 255 - tid;
            int v = hist[r];
            #pragma unroll
            for (int o = 1; o < 32; o <<= 1) {
                int t = __shfl_up_sync(0xffffffffu, v, o);
                if (lane >= o) v += t;
            }
            if (lane == 31) wsum[tid >> 5] = v;
            __syncthreads();
            int add = 0;
            #pragma unroll
            for (int w = 0; w < 8; w++) add += (w < (tid >> 5)) ? wsum[w] : 0;
            int suf   = v + add;              // inclusive suffix count at bin r
            int k     = s_k;
            int above = suf - hist[r];        // strictly-above count
            if (suf >= k && above < k) {      // exactly one thread fires
                s_k = k - above;
                s_prefix = prefix | ((unsigned)r << shift);
            }
        }
        __syncthreads();
    }

    const unsigned kthkey = s_prefix;
    for (int i = tid; i < MM; i += 256) {
        unsigned u = __ldg(&keys[i]);
        if (u >= kthkey) {
            int p = atomicAdd(&s_cnt, 1);
            if (p < SEL_CAP) { s_idx[p] = i; s_w[p] = k2f(u); }
        }
    }
    __syncthreads();

    int n = s_cnt; if (n > SEL_CAP) n = SEL_CAP;

    // sum of w^2 (one warp)
    if (tid < 32) {
        float sw2 = 0.f;
        for (int i = tid; i < n; i += 32) { float w = s_w[i]; sw2 += w * w; }
        #pragma unroll
        for (int o = 16; o; o >>= 1) sw2 += __shfl_xor_sync(0xffffffffu, sw2, o);
        if (tid == 0) s_sw2 = sw2;
    }

    // read: 2 groups of 128 threads; unrolled predicated gather (L2-hot rows)
    const int vcol = tid & (VV - 1);
    const int grp  = tid >> 7;
    float acc = 0.f;
    #pragma unroll
    for (int c = 0; c < 40; c++) {            // covers n <= 80 unrolled
        int i = grp + c * 2;
        if (i < n) {
            int   m = s_idx[i];
            float w = s_w[i];
            acc += w * mem[((size_t)b * MM + m) * VV + vcol];
        }
    }
    for (int i = grp + 80; i < n; i += 2) {   // tie-overflow tail (rare)
        int   m = s_idx[i];
        float w = s_w[i];
        acc += w * mem[((size_t)b * MM + m) * VV + vcol];
    }
    s_part[grp][vcol] = acc;
    __syncthreads();

    if (tid < VV)
        out[b * VV + tid] = s_part[0][tid] + s_part[1][tid]
                            + s_sw2 * vin[b * VV + tid];

    // reset arrival counter for the next graph replay
    if (tid == 0) g_counter[b] = 0;
}

// ============================================================================
extern "C" void kernel_launch(void* const* d_in, const int* in_sizes, int n_in,
                              void* d_out, int out_size) {
    const float* mem  = (const float*)d_in[0];   // (B, M, V) f32
    const float* vin  = (const float*)d_in[1];   // (B, V)    f32
    const int*   topk = (const int*)d_in[2];     // scalar    i32
    float*       out  = (float*)d_out;           // (B,1,1,V) f32

    fused_kernel<<<dim3(BLOCKS_PER_B, BB), 256>>>(mem, vin, topk, out);
}

// round 10
// speedup vs baseline: 1.2024x; 1.2024x over previous
#include <cuda_runtime.h>
#include <cstdint>
#include <math.h>

#define BB 64
#define MM 8192
#define VV 128
#define FEPS 1e-8f
#define SEL_CAP 1024

// Scratch (device globals: no allocation allowed in kernel_launch)
__device__ float g_sim[BB * MM];   // 2 MB similarity per slot

// ---- order-preserving float<->uint key mapping (larger float => larger key) ----
__device__ __forceinline__ unsigned f2k(float f) {
    unsigned b = __float_as_uint(f);
    return (b & 0x80000000u) ? ~b : (b | 0x80000000u);
}
__device__ __forceinline__ float k2f(unsigned u) {
    unsigned b = (u & 0x80000000u) ? (u ^ 0x80000000u) : ~u;
    return __uint_as_float(b);
}

// ============================================================================
// Pass 1 (R6 proven, byte-identical): sim = dot(mem+eps, v+eps)/max(||.||², eps)
// 8 lanes/row, 4 rows/warp, 8 independent streaming LDG.128 per thread.
// 256 threads -> 64 rows/block. Grid: (MM/64, BB).
// ============================================================================
__global__ void __launch_bounds__(256) sim_kernel(const float* __restrict__ mem,
                                                  const float* __restrict__ vin) {
    __shared__ __align__(16) float sv[VV];
    __shared__ float s_nb;
    const int b   = blockIdx.y;
    const int tid = threadIdx.x;

    if (tid < VV) sv[tid] = vin[b * VV + tid] + FEPS;
    __syncthreads();
    if (tid < 32) {
        float s = 0.f;
        #pragma unroll
        for (int i = tid; i < VV; i += 32) { float x = sv[i]; s += x * x; }
        #pragma unroll
        for (int o = 16; o; o >>= 1) s += __shfl_xor_sync(0xffffffffu, s, o);
        if (tid == 0) s_nb = sqrtf(s);
    }
    __syncthreads();

    const float nb   = s_nb;
    const int   warp = tid >> 5;
    const int   lane = tid & 31;
    const int   rw   = lane >> 3;   // row within warp's 4-row group
    const int   s    = lane & 7;    // float4 segment within row (0..7)

    const float4* svq = reinterpret_cast<const float4*>(sv);
    const float4 q0 = svq[s], q1 = svq[s + 8], q2 = svq[s + 16], q3 = svq[s + 24];

    const int m0 = blockIdx.x * 64 + warp * 4 + rw;
    const int m1 = m0 + 32;
    const float4* rowA = reinterpret_cast<const float4*>(mem + ((size_t)b * MM + m0) * VV);
    const float4* rowB = reinterpret_cast<const float4*>(mem + ((size_t)b * MM + m1) * VV);

    float4 a0 = __ldcs(rowA + s);      float4 a1 = __ldcs(rowA + s + 8);
    float4 a2 = __ldcs(rowA + s + 16); float4 a3 = __ldcs(rowA + s + 24);
    float4 b0 = __ldcs(rowB + s);      float4 b1 = __ldcs(rowB + s + 8);
    float4 b2 = __ldcs(rowB + s + 16); float4 b3 = __ldcs(rowB + s + 24);

    float numA = 0.f, ssA = 0.f, numB = 0.f, ssB = 0.f;
    #define ACC(X, Q, NUM, SS)                                        \
        { float e0 = X.x + FEPS, e1 = X.y + FEPS,                     \
                e2 = X.z + FEPS, e3 = X.w + FEPS;                     \
          NUM += e0 * Q.x + e1 * Q.y + e2 * Q.z + e3 * Q.w;           \
          SS  += e0 * e0 + e1 * e1 + e2 * e2 + e3 * e3; }
    ACC(a0, q0, numA, ssA) ACC(a1, q1, numA, ssA)
    ACC(a2, q2, numA, ssA) ACC(a3, q3, numA, ssA)
    ACC(b0, q0, numB, ssB) ACC(b1, q1, numB, ssB)
    ACC(b2, q2, numB, ssB) ACC(b3, q3, numB, ssB)
    #undef ACC

    #pragma unroll
    for (int o = 4; o; o >>= 1) {
        numA += __shfl_xor_sync(0xffffffffu, numA, o);
        ssA  += __shfl_xor_sync(0xffffffffu, ssA,  o);
        numB += __shfl_xor_sync(0xffffffffu, numB, o);
        ssB  += __shfl_xor_sync(0xffffffffu, ssB,  o);
    }
    if (s == 0) {
        g_sim[b * MM + m0] = numA / fmaxf(sqrtf(ssA) * nb, FEPS);
        g_sim[b * MM + m1] = numB / fmaxf(sqrtf(ssB) * nb, FEPS);
    }
}

// ============================================================================
// Pass 2 (fused select + read, barrier-lean): keys in registers (8/thread).
// 4-round radix select with DOUBLE-BUFFERED histograms: the next round's
// buffer is cleared during the pick phase (threads 512-767) after pick
// threads snapshot their bins into registers -> 3 block barriers per round.
// sw2 accumulated by shared float atomics during compaction (no extra pass).
// Unrolled predicated gather (MLP 16). One block of 1024 threads per batch.
// ============================================================================
__global__ void __launch_bounds__(1024) select_read_kernel(
        const int* __restrict__ topk_ptr,
        const float* __restrict__ mem,
        const float* __restrict__ vin,
        float* __restrict__ out) {
    __shared__ int      hist[2][256];
    __shared__ int      wsum[8];
    __shared__ unsigned s_prefix;
    __shared__ int      s_k, s_cnt;
    __shared__ int      s_idx[SEL_CAP];
    __shared__ float    s_w[SEL_CAP];
    __shared__ float    s_part[8][VV];
    __shared__ float    s_sw2;

    const int b    = blockIdx.x;
    const int tid  = threadIdx.x;
    const int lane = tid & 31;

    // Load this thread's 8 keys into registers
    unsigned uk[8];
    #pragma unroll
    for (int j = 0; j < 8; j++)
        uk[j] = f2k(g_sim[b * MM + j * 1024 + tid]);

    if (tid == 0) { s_prefix = 0u; s_k = *topk_ptr; s_cnt = 0; s_sw2 = 0.f; }
    if (tid < 256) { hist[0][tid] = 0; hist[1][tid] = 0; }
    __syncthreads();

    #pragma unroll
    for (int round = 0; round < 4; round++) {
        const int cur   = round & 1;
        const int shift = 24 - 8 * round;
        const unsigned pmask  = (round == 0) ? 0u : (0xFFFFFFFFu << (shift + 8));
        const unsigned prefix = s_prefix;
        const int      kcur   = s_k;
        #pragma unroll
        for (int j = 0; j < 8; j++) {
            unsigned u = uk[j];
            if ((u & pmask) == prefix)
                atomicAdd(&hist[cur][(u >> shift) & 255], 1);
        }
        __syncthreads();
        // pick phase: threads 0-255 scan; after mid-sync threads 512-767 clear
        // hist[cur] for reuse two rounds later (pick threads hold reg copies).
        {
            const int r = 255 - tid;             // valid for tid < 256
            int h = 0, v = 0;
            if (tid < 256) {
                h = hist[cur][r];
                v = h;
                #pragma unroll
                for (int o = 1; o < 32; o <<= 1) {
                    int t = __shfl_up_sync(0xffffffffu, v, o);
                    if (lane >= o) v += t;
                }
                if (lane == 31) wsum[tid >> 5] = v;
            }
            __syncthreads();                     // wsum ready; hist reads done
            if (tid < 256) {
                int add = 0;
                #pragma unroll
                for (int w = 0; w < 8; w++) add += (w < (tid >> 5)) ? wsum[w] : 0;
                int suf   = v + add;             // inclusive suffix count at bin r
                int above = suf - h;             // count strictly above bin r
                if (suf >= kcur && above < kcur) {   // exactly one thread fires
                    s_k = kcur - above;
                    s_prefix = prefix | ((unsigned)r << shift);
                }
            } else if (tid >= 512 && tid < 768) {
                hist[cur][tid - 512] = 0;        // clear for round+2
            }
        }
        __syncthreads();
    }

    // compaction + sw2 (float shared atomics; ~topk ops total)
    const unsigned kthkey = s_prefix;
    #pragma unroll
    for (int j = 0; j < 8; j++) {
        unsigned u = uk[j];
        if (u >= kthkey) {
            int p = atomicAdd(&s_cnt, 1);
            float w = k2f(u);
            if (p < SEL_CAP) { s_idx[p] = j * 1024 + tid; s_w[p] = w; }
            atomicAdd(&s_sw2, w * w);
        }
    }
    __syncthreads();

    int n = s_cnt; if (n > SEL_CAP) n = SEL_CAP;

    // read: 8 groups of 128 threads; unrolled predicated gather (MLP 16)
    const int vcol = tid & (VV - 1);
    const int grp  = tid >> 7;
    float acc = 0.f;
    #pragma unroll
    for (int c = 0; c < 16; c++) {
        int i = grp + c * 8;
        if (i < n) {
            int   m = s_idx[i];
            float w = s_w[i];
            acc += w * mem[((size_t)b * MM + m) * VV + vcol];
        }
    }
    for (int i = grp + 128; i < n; i += 8) {   // tie-overflow tail (rare)
        int   m = s_idx[i];
        float w = s_w[i];
        acc += w * mem[((size_t)b * MM + m) * VV + vcol];
    }
    s_part[grp][vcol] = acc;
    __syncthreads();

    if (tid < VV) {
        float a = 0.f;
        #pragma unroll
        for (int g = 0; g < 8; g++) a += s_part[g][tid];
        out[b * VV + tid] = a + s_sw2 * vin[b * VV + tid];
    }
}

// ============================================================================
extern "C" void kernel_launch(void* const* d_in, const int* in_sizes, int n_in,
                              void* d_out, int out_size) {
    const float* mem  = (const float*)d_in[0];   // (B, M, V) f32
    const float* vin  = (const float*)d_in[1];   // (B, V)    f32
    const int*   topk = (const int*)d_in[2];     // scalar    i32
    float*       out  = (float*)d_out;           // (B,1,1,V) f32

    sim_kernel<<<dim3(MM / 64, BB), 256>>>(mem, vin);
    select_read_kernel<<<BB, 1024>>>(topk, mem, vin, out);
}

// round 11
// speedup vs baseline: 1.2031x; 1.0006x over previous
#include <cuda_runtime.h>
#include <cstdint>
#include <math.h>

#define BB 64
#define MM 8192
#define VV 128
#define FEPS 1e-8f
#define SEL_CAP 1024

// Scratch (device globals: no allocation allowed in kernel_launch)
__device__ float g_sim[BB * MM];   // 2 MB similarity per slot

// ---- order-preserving float<->uint key mapping (larger float => larger key) ----
__device__ __forceinline__ unsigned f2k(float f) {
    unsigned b = __float_as_uint(f);
    return (b & 0x80000000u) ? ~b : (b | 0x80000000u);
}
__device__ __forceinline__ float k2f(unsigned u) {
    unsigned b = (u & 0x80000000u) ? (u ^ 0x80000000u) : ~u;
    return __uint_as_float(b);
}

// ============================================================================
// Pass 1: BARRIER-FREE, SMEM-FREE sim kernel.
// sim[b,m] = dot(mem[b,m]+eps, v[b]+eps) / max(||mem+eps||*||v+eps||, eps)
// Each lane loads its 4 q-float4s straight from vin (L1-hot, 512B/batch).
// Across a warp, the 32 lanes' q segments cover all 32 float4s exactly 4x, so
// a 5-shfl warp reduction gives 4*||v+eps||^2 -> nb = sqrt(0.25*sum).
// Row LDGs are independent of q and issue immediately (no prologue barrier).
// 8 lanes/row, 4 rows/warp, 8 independent streaming LDG.128 per thread.
// 256 threads -> 64 rows/block. Grid: (MM/64, BB).
// ============================================================================
__global__ void __launch_bounds__(256) sim_kernel(const float* __restrict__ mem,
                                                  const float* __restrict__ vin) {
    const int b    = blockIdx.y;
    const int tid  = threadIdx.x;
    const int warp = tid >> 5;
    const int lane = tid & 31;
    const int rw   = lane >> 3;   // row within warp's 4-row group
    const int s    = lane & 7;    // float4 segment within row (0..7)

    const int m0 = blockIdx.x * 64 + warp * 4 + rw;
    const int m1 = m0 + 32;
    const float4* rowA = reinterpret_cast<const float4*>(mem + ((size_t)b * MM + m0) * VV);
    const float4* rowB = reinterpret_cast<const float4*>(mem + ((size_t)b * MM + m1) * VV);

    // 8 independent streaming 16B row loads issue first (the DRAM stream)
    float4 a0 = __ldcs(rowA + s);      float4 a1 = __ldcs(rowA + s + 8);
    float4 a2 = __ldcs(rowA + s + 16); float4 a3 = __ldcs(rowA + s + 24);
    float4 b0 = __ldcs(rowB + s);      float4 b1 = __ldcs(rowB + s + 8);
    float4 b2 = __ldcs(rowB + s + 16); float4 b3 = __ldcs(rowB + s + 24);

    // q loads (L1/L2-hot, independent of row loads)
    const float4* vq = reinterpret_cast<const float4*>(vin + b * VV);
    float4 q0 = __ldg(vq + s);      float4 q1 = __ldg(vq + s + 8);
    float4 q2 = __ldg(vq + s + 16); float4 q3 = __ldg(vq + s + 24);
    q0.x += FEPS; q0.y += FEPS; q0.z += FEPS; q0.w += FEPS;
    q1.x += FEPS; q1.y += FEPS; q1.z += FEPS; q1.w += FEPS;
    q2.x += FEPS; q2.y += FEPS; q2.z += FEPS; q2.w += FEPS;
    q3.x += FEPS; q3.y += FEPS; q3.z += FEPS; q3.w += FEPS;

    // ||v+eps||^2: warp-sum of per-lane partials counts every element 4x
    float sq = q0.x * q0.x + q0.y * q0.y + q0.z * q0.z + q0.w * q0.w
             + q1.x * q1.x + q1.y * q1.y + q1.z * q1.z + q1.w * q1.w
             + q2.x * q2.x + q2.y * q2.y + q2.z * q2.z + q2.w * q2.w
             + q3.x * q3.x + q3.y * q3.y + q3.z * q3.z + q3.w * q3.w;
    #pragma unroll
    for (int o = 16; o; o >>= 1) sq += __shfl_xor_sync(0xffffffffu, sq, o);
    const float nb = sqrtf(0.25f * sq);

    float numA = 0.f, ssA = 0.f, numB = 0.f, ssB = 0.f;
    #define ACC(X, Q, NUM, SS)                                        \
        { float e0 = X.x + FEPS, e1 = X.y + FEPS,                     \
                e2 = X.z + FEPS, e3 = X.w + FEPS;                     \
          NUM += e0 * Q.x + e1 * Q.y + e2 * Q.z + e3 * Q.w;           \
          SS  += e0 * e0 + e1 * e1 + e2 * e2 + e3 * e3; }
    ACC(a0, q0, numA, ssA) ACC(a1, q1, numA, ssA)
    ACC(a2, q2, numA, ssA) ACC(a3, q3, numA, ssA)
    ACC(b0, q0, numB, ssB) ACC(b1, q1, numB, ssB)
    ACC(b2, q2, numB, ssB) ACC(b3, q3, numB, ssB)
    #undef ACC

    // reduce across the 8 lanes of each row (xor 1,2,4)
    #pragma unroll
    for (int o = 4; o; o >>= 1) {
        numA += __shfl_xor_sync(0xffffffffu, numA, o);
        ssA  += __shfl_xor_sync(0xffffffffu, ssA,  o);
        numB += __shfl_xor_sync(0xffffffffu, numB, o);
        ssB  += __shfl_xor_sync(0xffffffffu, ssB,  o);
    }
    if (s == 0) {
        g_sim[b * MM + m0] = numA / fmaxf(sqrtf(ssA) * nb, FEPS);
        g_sim[b * MM + m1] = numB / fmaxf(sqrtf(ssB) * nb, FEPS);
    }
}

// ============================================================================
// Pass 2 (fused select + read) — EXACT R6 structure (best measured: 9.6us).
// Keys in registers (8/thread). 4-round 8-bit MSB radix select with plain
// shared atomics + parallel suffix-scan bin pick. Compaction, then
//   out[b,:] = sum_sel w*mem[b,m,:] + (sum_sel w^2)*v[b,:]
// One block of 1024 threads per batch.
// ============================================================================
__global__ void __launch_bounds__(1024) select_read_kernel(
        const int* __restrict__ topk_ptr,
        const float* __restrict__ mem,
        const float* __restrict__ vin,
        float* __restrict__ out) {
    __shared__ int      hist[256];
    __shared__ int      wsum[8];
    __shared__ unsigned s_prefix;
    __shared__ int      s_k, s_cnt;
    __shared__ int      s_idx[SEL_CAP];
    __shared__ float    s_w[SEL_CAP];
    __shared__ float    s_part[8][VV];
    __shared__ float    s_sw2;

    const int b    = blockIdx.x;
    const int tid  = threadIdx.x;
    const int lane = tid & 31;

    // Load this thread's 8 keys into registers
    unsigned uk[8];
    #pragma unroll
    for (int j = 0; j < 8; j++)
        uk[j] = f2k(g_sim[b * MM + j * 1024 + tid]);

    if (tid == 0) { s_prefix = 0u; s_k = *topk_ptr; s_cnt = 0; }
    __syncthreads();

    #pragma unroll
    for (int shift = 24; shift >= 0; shift -= 8) {
        if (tid < 256) hist[tid] = 0;
        __syncthreads();
        const unsigned pmask  = (shift == 24) ? 0u : (0xFFFFFFFFu << (shift + 8));
        const unsigned prefix = s_prefix;
        #pragma unroll
        for (int j = 0; j < 8; j++) {
            unsigned u = uk[j];
            if ((u & pmask) == prefix)
                atomicAdd(&hist[(u >> shift) & 255], 1);
        }
        __syncthreads();
        // Parallel suffix-sum over bins (descending): thread t handles bin r=255-t.
        {
            const int r = 255 - tid;             // valid for tid < 256
            int v = (tid < 256) ? hist[r] : 0;
            #pragma unroll
            for (int o = 1; o < 32; o <<= 1) {
                int t = __shfl_up_sync(0xffffffffu, v, o);
                if (lane >= o) v += t;
            }
            if (tid < 256 && lane == 31) wsum[tid >> 5] = v;
            __syncthreads();
            if (tid < 256) {
                int add = 0;
                #pragma unroll
                for (int w = 0; w < 8; w++) add += (w < (tid >> 5)) ? wsum[w] : 0;
                int suf = v + add;               // inclusive suffix count at bin r
                int k   = s_k;
                int above = suf - hist[r];       // count in bins strictly above r
                if (suf >= k && above < k) {     // exactly one thread fires
                    s_k = k - above;
                    s_prefix = s_prefix | ((unsigned)r << shift);
                }
            }
        }
        __syncthreads();
    }

    const unsigned kthkey = s_prefix;
    #pragma unroll
    for (int j = 0; j < 8; j++) {
        unsigned u = uk[j];
        if (u >= kthkey) {
            int p = atomicAdd(&s_cnt, 1);
            if (p < SEL_CAP) { s_idx[p] = j * 1024 + tid; s_w[p] = k2f(u); }
        }
    }
    __syncthreads();

    int n = s_cnt; if (n > SEL_CAP) n = SEL_CAP;

    // sum of w^2 (one warp)
    if (tid < 32) {
        float sw2 = 0.f;
        for (int i = tid; i < n; i += 32) { float w = s_w[i]; sw2 += w * w; }
        #pragma unroll
        for (int o = 16; o; o >>= 1) sw2 += __shfl_xor_sync(0xffffffffu, sw2, o);
        if (tid == 0) s_sw2 = sw2;
    }

    // read: 8 groups of 128 threads accumulate over selected rows
    const int vcol = tid & (VV - 1);
    const int grp  = tid >> 7;
    float acc = 0.f;
    for (int i = grp; i < n; i += 8) {
        int   m = s_idx[i];
        float w = s_w[i];
        acc += w * mem[((size_t)b * MM + m) * VV + vcol];
    }
    s_part[grp][vcol] = acc;
    __syncthreads();

    if (tid < VV) {
        float a = 0.f;
        #pragma unroll
        for (int g = 0; g < 8; g++) a += s_part[g][tid];
        out[b * VV + tid] = a + s_sw2 * vin[b * VV + tid];
    }
}

// ============================================================================
extern "C" void kernel_launch(void* const* d_in, const int* in_sizes, int n_in,
                              void* d_out, int out_size) {
    const float* mem  = (const float*)d_in[0];   // (B, M, V) f32
    const float* vin  = (const float*)d_in[1];   // (B, V)    f32
    const int*   topk = (const int*)d_in[2];     // scalar    i32
    float*       out  = (float*)d_out;           // (B,1,1,V) f32

    sim_kernel<<<dim3(MM / 64, BB), 256>>>(mem, vin);
    select_read_kernel<<<BB, 1024>>>(topk, mem, vin, out);
}

// round 12
// speedup vs baseline: 1.2519x; 1.0406x over previous
#include <cuda_runtime.h>
#include <cstdint>
#include <math.h>

#define BB 64
#define MM 8192
#define VV 128
#define FEPS 1e-8f
#define SEL_CAP 1024

// Scratch (device globals: no allocation allowed in kernel_launch)
__device__ float g_sim[BB * MM];   // 2 MB similarity per slot

// ---- order-preserving float<->uint key mapping (larger float => larger key) ----
__device__ __forceinline__ unsigned f2k(float f) {
    unsigned b = __float_as_uint(f);
    return (b & 0x80000000u) ? ~b : (b | 0x80000000u);
}
__device__ __forceinline__ float k2f(unsigned u) {
    unsigned b = (u & 0x80000000u) ? (u ^ 0x80000000u) : ~u;
    return __uint_as_float(b);
}

// ============================================================================
// Pass 1 (R6 proven, byte-identical): sim = dot(mem+eps, v+eps)/max(||.||*||.||, eps)
// 8 lanes/row, 4 rows/warp, 8 independent streaming LDG.128 per thread.
// 256 threads -> 64 rows/block. Grid: (MM/64, BB).
// ============================================================================
__global__ void __launch_bounds__(256) sim_kernel(const float* __restrict__ mem,
                                                  const float* __restrict__ vin) {
    __shared__ __align__(16) float sv[VV];
    __shared__ float s_nb;
    const int b   = blockIdx.y;
    const int tid = threadIdx.x;

    if (tid < VV) sv[tid] = vin[b * VV + tid] + FEPS;
    __syncthreads();
    if (tid < 32) {
        float s = 0.f;
        #pragma unroll
        for (int i = tid; i < VV; i += 32) { float x = sv[i]; s += x * x; }
        #pragma unroll
        for (int o = 16; o; o >>= 1) s += __shfl_xor_sync(0xffffffffu, s, o);
        if (tid == 0) s_nb = sqrtf(s);
    }
    __syncthreads();

    const float nb   = s_nb;
    const int   warp = tid >> 5;
    const int   lane = tid & 31;
    const int   rw   = lane >> 3;   // row within warp's 4-row group
    const int   s    = lane & 7;    // float4 segment within row (0..7)

    const float4* svq = reinterpret_cast<const float4*>(sv);
    const float4 q0 = svq[s], q1 = svq[s + 8], q2 = svq[s + 16], q3 = svq[s + 24];

    const int m0 = blockIdx.x * 64 + warp * 4 + rw;
    const int m1 = m0 + 32;
    const float4* rowA = reinterpret_cast<const float4*>(mem + ((size_t)b * MM + m0) * VV);
    const float4* rowB = reinterpret_cast<const float4*>(mem + ((size_t)b * MM + m1) * VV);

    float4 a0 = __ldcs(rowA + s);      float4 a1 = __ldcs(rowA + s + 8);
    float4 a2 = __ldcs(rowA + s + 16); float4 a3 = __ldcs(rowA + s + 24);
    float4 b0 = __ldcs(rowB + s);      float4 b1 = __ldcs(rowB + s + 8);
    float4 b2 = __ldcs(rowB + s + 16); float4 b3 = __ldcs(rowB + s + 24);

    float numA = 0.f, ssA = 0.f, numB = 0.f, ssB = 0.f;
    #define ACC(X, Q, NUM, SS)                                        \
        { float e0 = X.x + FEPS, e1 = X.y + FEPS,                     \
                e2 = X.z + FEPS, e3 = X.w + FEPS;                     \
          NUM += e0 * Q.x + e1 * Q.y + e2 * Q.z + e3 * Q.w;           \
          SS  += e0 * e0 + e1 * e1 + e2 * e2 + e3 * e3; }
    ACC(a0, q0, numA, ssA) ACC(a1, q1, numA, ssA)
    ACC(a2, q2, numA, ssA) ACC(a3, q3, numA, ssA)
    ACC(b0, q0, numB, ssB) ACC(b1, q1, numB, ssB)
    ACC(b2, q2, numB, ssB) ACC(b3, q3, numB, ssB)
    #undef ACC

    #pragma unroll
    for (int o = 4; o; o >>= 1) {
        numA += __shfl_xor_sync(0xffffffffu, numA, o);
        ssA  += __shfl_xor_sync(0xffffffffu, ssA,  o);
        numB += __shfl_xor_sync(0xffffffffu, numB, o);
        ssB  += __shfl_xor_sync(0xffffffffu, ssB,  o);
    }
    if (s == 0) {
        g_sim[b * MM + m0] = numA / fmaxf(sqrtf(ssA) * nb, FEPS);
        g_sim[b * MM + m1] = numB / fmaxf(sqrtf(ssB) * nb, FEPS);
    }
}

// ============================================================================
// Pass 2 (fused select + read) — R6 structure; ONLY change: the gather loop is
// a 16-step predicated unroll (independent LDGs, MLP 16) instead of a serial
// runtime-bound loop, with a tie-overflow tail for n > 128.
// One block of 1024 threads per batch.
// ============================================================================
__global__ void __launch_bounds__(1024) select_read_kernel(
        const int* __restrict__ topk_ptr,
        const float* __restrict__ mem,
        const float* __restrict__ vin,
        float* __restrict__ out) {
    __shared__ int      hist[256];
    __shared__ int      wsum[8];
    __shared__ unsigned s_prefix;
    __shared__ int      s_k, s_cnt;
    __shared__ int      s_idx[SEL_CAP];
    __shared__ float    s_w[SEL_CAP];
    __shared__ float    s_part[8][VV];
    __shared__ float    s_sw2;

    const int b    = blockIdx.x;
    const int tid  = threadIdx.x;
    const int lane = tid & 31;

    // Load this thread's 8 keys into registers
    unsigned uk[8];
    #pragma unroll
    for (int j = 0; j < 8; j++)
        uk[j] = f2k(g_sim[b * MM + j * 1024 + tid]);

    if (tid == 0) { s_prefix = 0u; s_k = *topk_ptr; s_cnt = 0; }
    __syncthreads();

    #pragma unroll
    for (int shift = 24; shift >= 0; shift -= 8) {
        if (tid < 256) hist[tid] = 0;
        __syncthreads();
        const unsigned pmask  = (shift == 24) ? 0u : (0xFFFFFFFFu << (shift + 8));
        const unsigned prefix = s_prefix;
        #pragma unroll
        for (int j = 0; j < 8; j++) {
            unsigned u = uk[j];
            if ((u & pmask) == prefix)
                atomicAdd(&hist[(u >> shift) & 255], 1);
        }
        __syncthreads();
        // Parallel suffix-sum over bins (descending): thread t handles bin r=255-t.
        {
            const int r = 255 - tid;             // valid for tid < 256
            int v = (tid < 256) ? hist[r] : 0;
            #pragma unroll
            for (int o = 1; o < 32; o <<= 1) {
                int t = __shfl_up_sync(0xffffffffu, v, o);
                if (lane >= o) v += t;
            }
            if (tid < 256 && lane == 31) wsum[tid >> 5] = v;
            __syncthreads();
            if (tid < 256) {
                int add = 0;
                #pragma unroll
                for (int w = 0; w < 8; w++) add += (w < (tid >> 5)) ? wsum[w] : 0;
                int suf = v + add;               // inclusive suffix count at bin r
                int k   = s_k;
                int above = suf - hist[r];       // count in bins strictly above r
                if (suf >= k && above < k) {     // exactly one thread fires
                    s_k = k - above;
                    s_prefix = s_prefix | ((unsigned)r << shift);
                }
            }
        }
        __syncthreads();
    }

    const unsigned kthkey = s_prefix;
    #pragma unroll
    for (int j = 0; j < 8; j++) {
        unsigned u = uk[j];
        if (u >= kthkey) {
            int p = atomicAdd(&s_cnt, 1);
            if (p < SEL_CAP) { s_idx[p] = j * 1024 + tid; s_w[p] = k2f(u); }
        }
    }
    __syncthreads();

    int n = s_cnt; if (n > SEL_CAP) n = SEL_CAP;

    // sum of w^2 (one warp)
    if (tid < 32) {
        float sw2 = 0.f;
        for (int i = tid; i < n; i += 32) { float w = s_w[i]; sw2 += w * w; }
        #pragma unroll
        for (int o = 16; o; o >>= 1) sw2 += __shfl_xor_sync(0xffffffffu, sw2, o);
        if (tid == 0) s_sw2 = sw2;
    }

    // read: 8 groups of 128 threads; PREDICATED UNROLLED gather (MLP 16)
    const int vcol = tid & (VV - 1);
    const int grp  = tid >> 7;
    float acc = 0.f;
    #pragma unroll
    for (int c = 0; c < 16; c++) {
        const int i = grp + c * 8;
        const bool p = (i < n);
        int   m = p ? s_idx[i] : 0;
        float w = p ? s_w[i]   : 0.f;
        float x = p ? mem[((size_t)b * MM + m) * VV + vcol] : 0.f;
        acc += w * x;
    }
    for (int i = grp + 128; i < n; i += 8) {   // tie-overflow tail (rare)
        int   m = s_idx[i];
        float w = s_w[i];
        acc += w * mem[((size_t)b * MM + m) * VV + vcol];
    }
    s_part[grp][vcol] = acc;
    __syncthreads();

    if (tid < VV) {
        float a = 0.f;
        #pragma unroll
        for (int g = 0; g < 8; g++) a += s_part[g][tid];
        out[b * VV + tid] = a + s_sw2 * vin[b * VV + tid];
    }
}

// ============================================================================
extern "C" void kernel_launch(void* const* d_in, const int* in_sizes, int n_in,
                              void* d_out, int out_size) {
    const float* mem  = (const float*)d_in[0];   // (B, M, V) f32
    const float* vin  = (const float*)d_in[1];   // (B, V)    f32
    const int*   topk = (const int*)d_in[2];     // scalar    i32
    float*       out  = (float*)d_out;           // (B,1,1,V) f32

    sim_kernel<<<dim3(MM / 64, BB), 256>>>(mem, vin);
    select_read_kernel<<<BB, 1024>>>(topk, mem, vin, out);
}